// round 12
// baseline (speedup 1.0000x reference)
#include <cuda_runtime.h>
#include <cuda_bf16.h>
#include <cstdint>

// Problem constants (PointNetFeaturePropagation_5609227289179)
#define BB   4
#define NN   16384
#define SS   4096
#define D1   128
#define D2   256
#define C1   384
#define O1   256
#define O2   128
#define MTOT (BB*NN)   // 65536

// ---------------------------------------------------------------------------
// Scratch (device globals — no allocation allowed)
// ---------------------------------------------------------------------------
__device__ __align__(16) float g_p2w[BB * SS * O1];   // points2 @ W1b^T [16384,256]
__device__ __align__(16) float g_h1 [MTOT * O1];      // layer1 pre-BN   [65536,256]
__device__ __align__(16) int   g_idx[MTOT * 3];
__device__ __align__(16) float g_w  [MTOT * 3];
__device__ __align__(16) __nv_bfloat16 g_b0h[O1 * D2], g_b0l[O1 * D2];  // W1b split
__device__ __align__(16) __nv_bfloat16 g_b1h[O1 * D1], g_b1l[O1 * D1];  // W1a split
__device__ __align__(16) __nv_bfloat16 g_b2h[O2 * O1], g_b2l[O2 * O1];  // W2 split
__device__ float g_sum1[O1], g_sq1[O1];
__device__ float g_sum2[O2], g_sq2[O2];

// ---------------------------------------------------------------------------
__global__ void zero_stats_kernel() {
    int t = threadIdx.x;
    if (t < O1) { g_sum1[t] = 0.f; g_sq1[t] = 0.f; }
    if (t < O2) { g_sum2[t] = 0.f; g_sq2[t] = 0.f; }
}

// Pre-split weights into bf16 hi/lo
__global__ void prep_weights_kernel(const float* __restrict__ W1,
                                    const float* __restrict__ W2) {
    int idx = blockIdx.x * 256 + threadIdx.x;
    if (idx < O1 * C1) {
        int o = idx / C1, k = idx - o * C1;
        float v = W1[idx];
        __nv_bfloat16 h = __float2bfloat16(v);
        __nv_bfloat16 l = __float2bfloat16(v - __bfloat162float(h));
        if (k < D1) { g_b1h[o * D1 + k] = h; g_b1l[o * D1 + k] = l; }
        else        { g_b0h[o * D2 + k - D1] = h; g_b0l[o * D2 + k - D1] = l; }
    }
    if (idx < O2 * O1) {
        float v = W2[idx];
        __nv_bfloat16 h = __float2bfloat16(v);
        __nv_bfloat16 l = __float2bfloat16(v - __bfloat162float(h));
        g_b2h[idx] = h; g_b2l[idx] = l;
    }
}

// ---------------------------------------------------------------------------
// 3-NN: ordering key d' = ||p||^2 - 2 q.p, with (-2x,-2y,-2z,||p||^2) staged
// in smem -> 3 FMA per candidate. Pairwise fmin pre-filter cuts compare cost.
// ---------------------------------------------------------------------------
__global__ __launch_bounds__(256) void knn_kernel(
    const float* __restrict__ xyz1, const float* __restrict__ xyz2,
    int* __restrict__ oidx, float* __restrict__ ow)
{
    __shared__ float4 sp[2048];
    const int b = blockIdx.y;
    const int n = blockIdx.x * 256 + threadIdx.x;

    const float* q = xyz1 + ((size_t)b * NN + n) * 3;
    const float qx = q[0], qy = q[1], qz = q[2];

    float b0v = 1e30f, b1v = 1e30f, b2v = 1e30f;
    int   i0 = 0, i1 = 0, i2 = 0;

    auto insert = [&](float d, int s) {
        if (d < b2v) {
            if (d < b1v) {
                b2v = b1v; i2 = i1;
                if (d < b0v) { b1v = b0v; i1 = i0; b0v = d; i0 = s; }
                else         { b1v = d;  i1 = s; }
            } else { b2v = d; i2 = s; }
        }
    };

    for (int c0 = 0; c0 < SS; c0 += 2048) {
        __syncthreads();
        #pragma unroll
        for (int r = 0; r < 8; r++) {
            int s = threadIdx.x + r * 256;
            const float* p = xyz2 + ((size_t)b * SS + c0 + s) * 3;
            float x = p[0], y = p[1], z = p[2];
            sp[s] = make_float4(-2.f * x, -2.f * y, -2.f * z, x * x + y * y + z * z);
        }
        __syncthreads();

        #pragma unroll 4
        for (int j = 0; j < 2048; j += 2) {
            float4 p0 = sp[j];
            float4 p1 = sp[j + 1];
            float d0 = fmaf(qx, p0.x, fmaf(qy, p0.y, fmaf(qz, p0.z, p0.w)));
            float d1 = fmaf(qx, p1.x, fmaf(qy, p1.y, fmaf(qz, p1.z, p1.w)));
            if (fminf(d0, d1) < b2v) {
                insert(d0, c0 + j);
                insert(d1, c0 + j + 1);
            }
        }
    }

    const float qn = qx * qx + qy * qy + qz * qz;
    float d0 = fmaxf(b0v + qn, 0.f);
    float d1 = fmaxf(b1v + qn, 0.f);
    float d2 = fmaxf(b2v + qn, 0.f);
    float r0 = 1.f / (d0 + 1e-8f);
    float r1 = 1.f / (d1 + 1e-8f);
    float r2 = 1.f / (d2 + 1e-8f);
    float inv = 1.f / (r0 + r1 + r2);

    size_t o = ((size_t)b * NN + n) * 3;
    oidx[o + 0] = i0; oidx[o + 1] = i1; oidx[o + 2] = i2;
    ow[o + 0] = r0 * inv; ow[o + 1] = r1 * inv; ow[o + 2] = r2 * inv;
}

// ---------------------------------------------------------------------------
// bf16-split tensor-core GEMM via mma.sync.m16n8k16:
//   C[M,N] = A[M,K] @ Bw[N,K]^T,  D = Ah*Bh + Al*Bh + Ah*Bl  (fp32 accum)
// CTA tile 128x64, BK=64 (halves barrier count vs BK=32; per-chunk compute
// now covers the A-load latency), 8 warps (4x2) of 32x32. Double-buffered
// smem; ldmatrix.x4 fragment loads (row stride 144B -> conflict-free).
// MODE 0: plain
// MODE 1: +bias+3NN gather, fused stats out
// MODE 2: BN coeffs inline from (gsum_in,gsq_in,gamma,beta); BN+ReLU on A;
//         +bias; fused stats out
// ---------------------------------------------------------------------------
#define STRB  144         // smem row stride bytes (64 bf16 + 16B pad)
#define A_T   18432       // 128*144
#define B_T   9216        // 64*144
#define STGB  55296       // per-stage bytes: Ah,Al,Bh,Bl
#define SM_BIAS 110592
#define SM_SUM  110848
#define SM_SQ   111104
#define SM_SA   111360
#define SM_SC   112384
#define SM_SZ   113408

__device__ __forceinline__ void mma16816(float* d, const uint32_t* a, const uint32_t* b) {
    asm volatile(
        "mma.sync.aligned.m16n8k16.row.col.f32.bf16.bf16.f32 "
        "{%0,%1,%2,%3}, {%4,%5,%6,%7}, {%8,%9}, {%0,%1,%2,%3};"
        : "+f"(d[0]), "+f"(d[1]), "+f"(d[2]), "+f"(d[3])
        : "r"(a[0]), "r"(a[1]), "r"(a[2]), "r"(a[3]), "r"(b[0]), "r"(b[1]));
}
__device__ __forceinline__ void ldsm4(uint32_t* r, uint32_t addr) {
    asm volatile("ldmatrix.sync.aligned.m8n8.x4.shared.b16 {%0,%1,%2,%3}, [%4];"
        : "=r"(r[0]), "=r"(r[1]), "=r"(r[2]), "=r"(r[3]) : "r"(addr));
}
__device__ __forceinline__ uint32_t smem_u32(const void* p) {
    uint32_t a;
    asm("{ .reg .u64 t; cvta.to.shared.u64 t, %1; cvt.u32.u64 %0, t; }" : "=r"(a) : "l"(p));
    return a;
}
__device__ __forceinline__ uint32_t pack_hi2(float x, float y) {
    uint16_t hx = __bfloat16_as_ushort(__float2bfloat16(x));
    uint16_t hy = __bfloat16_as_ushort(__float2bfloat16(y));
    return (uint32_t)hx | ((uint32_t)hy << 16);
}
__device__ __forceinline__ uint32_t pack_lo2(float x, float y) {
    float hx = __bfloat162float(__float2bfloat16(x));
    float hy = __bfloat162float(__float2bfloat16(y));
    uint16_t lx = __bfloat16_as_ushort(__float2bfloat16(x - hx));
    uint16_t ly = __bfloat16_as_ushort(__float2bfloat16(y - hy));
    return (uint32_t)lx | ((uint32_t)ly << 16);
}

template<int MODE, int KTOT>
__global__ __launch_bounds__(256, 2) void mma_gemm(
    const float* __restrict__ A, int lda,
    const __nv_bfloat16* __restrict__ Bh, const __nv_bfloat16* __restrict__ Bl,
    float* __restrict__ C, int ldc,
    const float* __restrict__ bias,
    const float* __restrict__ gamma, const float* __restrict__ beta,
    const float* __restrict__ gsum_in, const float* __restrict__ gsq_in,
    const float* __restrict__ p2w, const int* __restrict__ gidx,
    const float* __restrict__ gw,
    float* __restrict__ gsum, float* __restrict__ gsq)
{
    extern __shared__ char sm[];
    const uint32_t sbase = smem_u32(sm);
    const int tid = threadIdx.x;
    const int m0 = blockIdx.y * 128;
    const int n0 = blockIdx.x * 64;

    float* sbias = (float*)(sm + SM_BIAS);
    float* ssum  = (float*)(sm + SM_SUM);
    float* ssq   = (float*)(sm + SM_SQ);
    float* sa    = (float*)(sm + SM_SA);
    float* sc    = (float*)(sm + SM_SC);
    if (MODE != 0 && tid < 64) sbias[tid] = bias[n0 + tid];
    if (MODE != 0 && tid < 128) { if (tid < 64) ssum[tid] = 0.f; else ssq[tid - 64] = 0.f; }
    if (MODE == 2 && tid < KTOT) {
        const float Minv = 1.f / (float)MTOT;
        float mean = gsum_in[tid] * Minv;
        float var  = fmaf(-mean, mean, gsq_in[tid] * Minv);
        float s = gamma[tid] * rsqrtf(var + 1e-5f);
        sa[tid] = s;
        sc[tid] = fmaf(-mean, s, beta[tid]);
    }
    __syncthreads();

    // gmem->reg prefetch mapping (BK=64)
    const int ra = tid >> 1, ka = (tid & 1) * 32;   // A: 128 rows x 64 k fp32
    const int rb = tid >> 2, kb2 = (tid & 3) * 16;  // B: 64 rows x 64 k bf16

    float4 av[8];
    uint4 bhv[2], blv[2];

    auto loadG = [&](int k0) {
        const float* ap = A + (size_t)(m0 + ra) * lda + k0 + ka;
        #pragma unroll
        for (int i = 0; i < 8; i++) av[i] = *(const float4*)(ap + i * 4);
        const __nv_bfloat16* bhp = Bh + (size_t)(n0 + rb) * KTOT + k0 + kb2;
        const __nv_bfloat16* blp = Bl + (size_t)(n0 + rb) * KTOT + k0 + kb2;
        bhv[0] = *(const uint4*)(bhp);
        bhv[1] = *(const uint4*)(bhp + 8);
        blv[0] = *(const uint4*)(blp);
        blv[1] = *(const uint4*)(blp + 8);
    };
    auto storeS = [&](int st, int k0) {
        char* base = sm + st * STGB;
        #pragma unroll
        for (int i = 0; i < 8; i++) {
            float4 v = av[i];
            if (MODE == 2) {
                int kg = k0 + ka + i * 4;
                v.x = fmaxf(fmaf(v.x, sa[kg + 0], sc[kg + 0]), 0.f);
                v.y = fmaxf(fmaf(v.y, sa[kg + 1], sc[kg + 1]), 0.f);
                v.z = fmaxf(fmaf(v.z, sa[kg + 2], sc[kg + 2]), 0.f);
                v.w = fmaxf(fmaf(v.w, sa[kg + 3], sc[kg + 3]), 0.f);
            }
            uint2 h2 = make_uint2(pack_hi2(v.x, v.y), pack_hi2(v.z, v.w));
            uint2 l2 = make_uint2(pack_lo2(v.x, v.y), pack_lo2(v.z, v.w));
            int ob = ra * STRB + (ka + i * 4) * 2;
            *(uint2*)(base + ob)       = h2;
            *(uint2*)(base + A_T + ob) = l2;
        }
        {
            int ob = rb * STRB + kb2 * 2;
            char* bh_ = base + 2 * A_T + ob;
            char* bl_ = bh_ + B_T;
            *(uint4*)(bh_)      = bhv[0];
            *(uint4*)(bh_ + 16) = bhv[1];
            *(uint4*)(bl_)      = blv[0];
            *(uint4*)(bl_ + 16) = blv[1];
        }
    };

    const int wid = tid >> 5, l = tid & 31;
    const int wm = (wid >> 1) * 32, wn = (wid & 1) * 32;
    const int lr = l >> 2, lc = l & 3;

    float acc[2][4][4];
    #pragma unroll
    for (int mi = 0; mi < 2; mi++)
        #pragma unroll
        for (int ni = 0; ni < 4; ni++)
            #pragma unroll
            for (int j = 0; j < 4; j++) acc[mi][ni][j] = 0.f;

    // ldmatrix per-lane base addresses (within stage 0)
    const uint32_t a_lane = sbase +
        (uint32_t)((wm + (l & 15)) * STRB + (l >> 4) * 16);
    const uint32_t b_lane = sbase +
        (uint32_t)(2 * A_T + (wn + (l & 7) + ((l >> 4) & 1) * 8) * STRB + ((l >> 3) & 1) * 16);

    auto comp = [&](int st) {
        const uint32_t ab = a_lane + st * STGB;
        const uint32_t bb = b_lane + st * STGB;
        #pragma unroll
        for (int ks = 0; ks < 4; ks++) {          // 4 k-steps of 16 (BK=64)
            uint32_t ah[2][4], al[2][4], bh[2][4], bl[2][4];
            #pragma unroll
            for (int mi = 0; mi < 2; mi++) {
                uint32_t a = ab + mi * (16 * STRB) + ks * 32;
                ldsm4(ah[mi], a);
                ldsm4(al[mi], a + A_T);
            }
            #pragma unroll
            for (int ni2 = 0; ni2 < 2; ni2++) {
                uint32_t b = bb + ni2 * (16 * STRB) + ks * 32;
                ldsm4(bh[ni2], b);
                ldsm4(bl[ni2], b + B_T);
            }
            #pragma unroll
            for (int mi = 0; mi < 2; mi++)
                #pragma unroll
                for (int ni = 0; ni < 4; ni++) {
                    const uint32_t* bhf = &bh[ni >> 1][(ni & 1) * 2];
                    const uint32_t* blf = &bl[ni >> 1][(ni & 1) * 2];
                    mma16816(acc[mi][ni], ah[mi], bhf);
                    mma16816(acc[mi][ni], al[mi], bhf);
                    mma16816(acc[mi][ni], ah[mi], blf);
                }
        }
    };

    constexpr int nch = KTOT / 64;
    loadG(0);
    storeS(0, 0);
    __syncthreads();
    #pragma unroll
    for (int kc = 0; kc < nch; kc++) {
        if (kc + 1 < nch) loadG((kc + 1) * 64);
        comp(kc & 1);
        if (kc + 1 < nch) {
            storeS((kc + 1) & 1, (kc + 1) * 64);
            __syncthreads();
        }
    }

    // --- epilogue: bias / gather / store + fused per-channel stats
    float fs[8], fq[8];
    #pragma unroll
    for (int i = 0; i < 8; i++) { fs[i] = 0.f; fq[i] = 0.f; }

    #pragma unroll
    for (int mi = 0; mi < 2; mi++) {
        #pragma unroll
        for (int half = 0; half < 2; half++) {
            const int gm = m0 + wm + mi * 16 + half * 8 + lr;
            const float *P0 = nullptr, *P1 = nullptr, *P2 = nullptr;
            float w0 = 0.f, w1 = 0.f, w2 = 0.f;
            if (MODE == 1) {
                const int bb_ = gm >> 14;                // NN = 16384
                int i0 = gidx[gm * 3 + 0], i1 = gidx[gm * 3 + 1], i2 = gidx[gm * 3 + 2];
                w0 = gw[gm * 3 + 0]; w1 = gw[gm * 3 + 1]; w2 = gw[gm * 3 + 2];
                P0 = p2w + ((size_t)bb_ * SS + i0) * O1 + n0;
                P1 = p2w + ((size_t)bb_ * SS + i1) * O1 + n0;
                P2 = p2w + ((size_t)bb_ * SS + i2) * O1 + n0;
            }
            float* Cp = C + (size_t)gm * ldc + n0;
            #pragma unroll
            for (int ni = 0; ni < 4; ni++) {
                const int col = wn + ni * 8 + lc * 2;
                float x = acc[mi][ni][half * 2 + 0];
                float y = acc[mi][ni][half * 2 + 1];
                if (MODE != 0) { x += sbias[col]; y += sbias[col + 1]; }
                if (MODE == 1) {
                    float2 q0 = *(const float2*)(P0 + col);
                    float2 q1 = *(const float2*)(P1 + col);
                    float2 q2 = *(const float2*)(P2 + col);
                    x += w0 * q0.x + w1 * q1.x + w2 * q2.x;
                    y += w0 * q0.y + w1 * q1.y + w2 * q2.y;
                }
                if (MODE != 0) {
                    fs[ni * 2 + 0] += x; fq[ni * 2 + 0] = fmaf(x, x, fq[ni * 2 + 0]);
                    fs[ni * 2 + 1] += y; fq[ni * 2 + 1] = fmaf(y, y, fq[ni * 2 + 1]);
                }
                *(float2*)(Cp + col) = make_float2(x, y);
            }
        }
    }

    if (MODE != 0) {
        #pragma unroll
        for (int i = 0; i < 8; i++) {
            fs[i] += __shfl_xor_sync(0xFFFFFFFFu, fs[i], 4);
            fs[i] += __shfl_xor_sync(0xFFFFFFFFu, fs[i], 8);
            fs[i] += __shfl_xor_sync(0xFFFFFFFFu, fs[i], 16);
            fq[i] += __shfl_xor_sync(0xFFFFFFFFu, fq[i], 4);
            fq[i] += __shfl_xor_sync(0xFFFFFFFFu, fq[i], 8);
            fq[i] += __shfl_xor_sync(0xFFFFFFFFu, fq[i], 16);
        }
        if (lr == 0) {
            #pragma unroll
            for (int ni = 0; ni < 4; ni++) {
                int col = wn + ni * 8 + lc * 2;
                atomicAdd(&ssum[col],     fs[ni * 2 + 0]);
                atomicAdd(&ssum[col + 1], fs[ni * 2 + 1]);
                atomicAdd(&ssq[col],      fq[ni * 2 + 0]);
                atomicAdd(&ssq[col + 1],  fq[ni * 2 + 1]);
            }
        }
        __syncthreads();
        if (tid < 64) {
            atomicAdd(&gsum[n0 + tid], ssum[tid]);
            atomicAdd(&gsq[n0 + tid],  ssq[tid]);
        }
    }
}

// ---------------------------------------------------------------------------
// Final BN2+ReLU apply, with inline coefficient computation.
// ---------------------------------------------------------------------------
__global__ void bnrelu_kernel(float* __restrict__ out,
                              const float* __restrict__ sum, const float* __restrict__ sq,
                              const float* __restrict__ gamma, const float* __restrict__ beta)
{
    __shared__ float sa[O2], sc[O2];
    const int tid = threadIdx.x;
    if (tid < O2) {
        const float Minv = 1.f / (float)MTOT;
        float mean = sum[tid] * Minv;
        float var  = fmaf(-mean, mean, sq[tid] * Minv);
        float s = gamma[tid] * rsqrtf(var + 1e-5f);
        sa[tid] = s;
        sc[tid] = fmaf(-mean, s, beta[tid]);
    }
    __syncthreads();

    const size_t i = (size_t)blockIdx.x * blockDim.x + tid;
    float4 v = ((float4*)out)[i];
    const int cb = (int)((i * 4) & (O2 - 1));
    v.x = fmaxf(fmaf(v.x, sa[cb + 0], sc[cb + 0]), 0.f);
    v.y = fmaxf(fmaf(v.y, sa[cb + 1], sc[cb + 1]), 0.f);
    v.z = fmaxf(fmaf(v.z, sa[cb + 2], sc[cb + 2]), 0.f);
    v.w = fmaxf(fmaf(v.w, sa[cb + 3], sc[cb + 3]), 0.f);
    ((float4*)out)[i] = v;
}

// ---------------------------------------------------------------------------
extern "C" void kernel_launch(void* const* d_in, const int* in_sizes, int n_in,
                              void* d_out, int out_size)
{
    const float* xyz1    = (const float*)d_in[0];
    const float* xyz2    = (const float*)d_in[1];
    const float* points1 = (const float*)d_in[2];
    const float* points2 = (const float*)d_in[3];
    const float* W1      = (const float*)d_in[4];
    const float* b1      = (const float*)d_in[5];
    const float* g1      = (const float*)d_in[6];
    const float* be1     = (const float*)d_in[7];
    const float* W2      = (const float*)d_in[8];
    const float* b2      = (const float*)d_in[9];
    const float* g2      = (const float*)d_in[10];
    const float* be2     = (const float*)d_in[11];
    float* out = (float*)d_out;

    float *p2w, *h1, *wp, *sum1, *sq1, *sum2, *sq2;
    int* idxp;
    __nv_bfloat16 *b0h, *b0l, *b1h, *b1l, *b2h, *b2l;
    cudaGetSymbolAddress((void**)&p2w,  g_p2w);
    cudaGetSymbolAddress((void**)&h1,   g_h1);
    cudaGetSymbolAddress((void**)&idxp, g_idx);
    cudaGetSymbolAddress((void**)&wp,   g_w);
    cudaGetSymbolAddress((void**)&sum1, g_sum1);
    cudaGetSymbolAddress((void**)&sq1,  g_sq1);
    cudaGetSymbolAddress((void**)&sum2, g_sum2);
    cudaGetSymbolAddress((void**)&sq2,  g_sq2);
    cudaGetSymbolAddress((void**)&b0h,  g_b0h);
    cudaGetSymbolAddress((void**)&b0l,  g_b0l);
    cudaGetSymbolAddress((void**)&b1h,  g_b1h);
    cudaGetSymbolAddress((void**)&b1l,  g_b1l);
    cudaGetSymbolAddress((void**)&b2h,  g_b2h);
    cudaGetSymbolAddress((void**)&b2l,  g_b2l);

    cudaFuncSetAttribute(mma_gemm<0, 256>, cudaFuncAttributeMaxDynamicSharedMemorySize, SM_SZ);
    cudaFuncSetAttribute(mma_gemm<1, 128>, cudaFuncAttributeMaxDynamicSharedMemorySize, SM_SZ);
    cudaFuncSetAttribute(mma_gemm<2, 256>, cudaFuncAttributeMaxDynamicSharedMemorySize, SM_SZ);

    // Side stream + events for knn overlap (created per call, intentionally
    // leaked: only a handful of invocations, and handles participate in capture).
    cudaStream_t s1;
    cudaEvent_t evFork, evJoin;
    cudaStreamCreateWithFlags(&s1, cudaStreamNonBlocking);
    cudaEventCreateWithFlags(&evFork, cudaEventDisableTiming);
    cudaEventCreateWithFlags(&evJoin, cudaEventDisableTiming);

    // Fork: knn runs on s1 concurrently with zero/prep/gemm0.
    cudaEventRecord(evFork, 0);
    cudaStreamWaitEvent(s1, evFork, 0);
    knn_kernel<<<dim3(NN / 256, BB), 256, 0, s1>>>(xyz1, xyz2, idxp, wp);
    cudaEventRecord(evJoin, s1);

    // Main stream: zero BN accumulators, weight split, P2W GEMM.
    zero_stats_kernel<<<1, 256>>>();
    prep_weights_kernel<<<(O1 * C1) / 256, 256>>>(W1, W2);
    mma_gemm<0, 256><<<dim3(O1 / 64, (BB * SS) / 128), 256, SM_SZ>>>(
        points2, D2, b0h, b0l, p2w, O1,
        nullptr, nullptr, nullptr, nullptr, nullptr, nullptr, nullptr, nullptr,
        nullptr, nullptr);

    // Join: gemm1 needs knn results.
    cudaStreamWaitEvent(0, evJoin, 0);

    // gemm1: h1 = points1 @ W1a^T + b1 + gather   (BN1 stats fused)
    mma_gemm<1, 128><<<dim3(O1 / 64, MTOT / 128), 256, SM_SZ>>>(
        points1, D1, b1h, b1l, h1, O1,
        b1, nullptr, nullptr, nullptr, nullptr, p2w, idxp, wp, sum1, sq1);

    // gemm2: out = relu(bn1(h1)) @ W2^T + b2   (BN1 coeffs inline, BN2 stats fused)
    mma_gemm<2, 256><<<dim3(O2 / 64, MTOT / 128), 256, SM_SZ>>>(
        h1, O1, b2h, b2l, out, O2,
        b2, g1, be1, sum1, sq1, nullptr, nullptr, nullptr, sum2, sq2);

    // BN2 + ReLU in place (coeffs inline)
    bnrelu_kernel<<<(MTOT * O2 / 4) / 256, 256>>>(out, sum2, sq2, g2, be2);
}

// round 15
// speedup vs baseline: 1.2076x; 1.2076x over previous
#include <cuda_runtime.h>
#include <cuda_bf16.h>
#include <cstdint>

// Problem constants (PointNetFeaturePropagation_5609227289179)
#define BB   4
#define NN   16384
#define SS   4096
#define D1   128
#define D2   256
#define C1   384
#define O1   256
#define O2   128
#define MTOT (BB*NN)   // 65536

// ---------------------------------------------------------------------------
// Scratch (device globals — no allocation allowed)
// ---------------------------------------------------------------------------
__device__ __align__(16) float g_p2w[BB * SS * O1];   // points2 @ W1b^T [16384,256]
__device__ __align__(16) float g_h1 [MTOT * O1];      // layer1 pre-BN   [65536,256]
__device__ __align__(16) int   g_idx[MTOT * 3];
__device__ __align__(16) float g_w  [MTOT * 3];
__device__ __align__(16) __nv_bfloat16 g_b0h[O1 * D2], g_b0l[O1 * D2];  // W1b split
__device__ __align__(16) __nv_bfloat16 g_b1h[O1 * D1], g_b1l[O1 * D1];  // W1a split
__device__ __align__(16) __nv_bfloat16 g_b2h[O2 * O1], g_b2l[O2 * O1];  // W2 split
__device__ __align__(16) __nv_bfloat16 g_a0h[BB * SS * D2], g_a0l[BB * SS * D2]; // points2 split
__device__ __align__(16) __nv_bfloat16 g_a1h[MTOT * D1],    g_a1l[MTOT * D1];    // points1 split
__device__ __align__(16) __nv_bfloat16 g_h2h[MTOT * O1],    g_h2l[MTOT * O1];    // bn1(h1) split
__device__ float g_sum1[O1], g_sq1[O1];
__device__ float g_sum2[O2], g_sq2[O2];

// ---------------------------------------------------------------------------
__global__ void zero_stats_kernel() {
    int t = threadIdx.x;
    if (t < O1) { g_sum1[t] = 0.f; g_sq1[t] = 0.f; }
    if (t < O2) { g_sum2[t] = 0.f; g_sq2[t] = 0.f; }
}

__device__ __forceinline__ uint32_t pack_hi2(float x, float y) {
    uint16_t hx = __bfloat16_as_ushort(__float2bfloat16(x));
    uint16_t hy = __bfloat16_as_ushort(__float2bfloat16(y));
    return (uint32_t)hx | ((uint32_t)hy << 16);
}
__device__ __forceinline__ uint32_t pack_lo2(float x, float y) {
    float hx = __bfloat162float(__float2bfloat16(x));
    float hy = __bfloat162float(__float2bfloat16(y));
    uint16_t lx = __bfloat16_as_ushort(__float2bfloat16(x - hx));
    uint16_t ly = __bfloat16_as_ushort(__float2bfloat16(y - hy));
    return (uint32_t)lx | ((uint32_t)ly << 16);
}

// Pre-split weights into bf16 hi/lo
__global__ void prep_weights_kernel(const float* __restrict__ W1,
                                    const float* __restrict__ W2) {
    int idx = blockIdx.x * 256 + threadIdx.x;
    if (idx < O1 * C1) {
        int o = idx / C1, k = idx - o * C1;
        float v = W1[idx];
        __nv_bfloat16 h = __float2bfloat16(v);
        __nv_bfloat16 l = __float2bfloat16(v - __bfloat162float(h));
        if (k < D1) { g_b1h[o * D1 + k] = h; g_b1l[o * D1 + k] = l; }
        else        { g_b0h[o * D2 + k - D1] = h; g_b0l[o * D2 + k - D1] = l; }
    }
    if (idx < O2 * O1) {
        float v = W2[idx];
        __nv_bfloat16 h = __float2bfloat16(v);
        __nv_bfloat16 l = __float2bfloat16(v - __bfloat162float(h));
        g_b2h[idx] = h; g_b2l[idx] = l;
    }
}

// Generic fp32 -> bf16 hi/lo elementwise split (4 floats/thread)
__global__ void split_kernel(const float4* __restrict__ src,
                             uint2* __restrict__ dh, uint2* __restrict__ dl)
{
    const size_t i = (size_t)blockIdx.x * 256 + threadIdx.x;
    float4 v = src[i];
    dh[i] = make_uint2(pack_hi2(v.x, v.y), pack_hi2(v.z, v.w));
    dl[i] = make_uint2(pack_lo2(v.x, v.y), pack_lo2(v.z, v.w));
}

// BN1 coeffs inline + ReLU + bf16 hi/lo split of h1 (layer-2 input prep)
__global__ void bnsplit_kernel(const float4* __restrict__ h1,
                               uint2* __restrict__ dh, uint2* __restrict__ dl,
                               const float* __restrict__ sum, const float* __restrict__ sq,
                               const float* __restrict__ gamma, const float* __restrict__ beta)
{
    __shared__ float sa[O1], sc[O1];
    const int tid = threadIdx.x;
    {
        const float Minv = 1.f / (float)MTOT;
        float mean = sum[tid] * Minv;
        float var  = fmaf(-mean, mean, sq[tid] * Minv);
        float s = gamma[tid] * rsqrtf(var + 1e-5f);
        sa[tid] = s;
        sc[tid] = fmaf(-mean, s, beta[tid]);
    }
    __syncthreads();
    const size_t i = (size_t)blockIdx.x * 256 + tid;
    float4 v = h1[i];
    const int cb = (int)((i * 4) & (O1 - 1));
    v.x = fmaxf(fmaf(v.x, sa[cb + 0], sc[cb + 0]), 0.f);
    v.y = fmaxf(fmaf(v.y, sa[cb + 1], sc[cb + 1]), 0.f);
    v.z = fmaxf(fmaf(v.z, sa[cb + 2], sc[cb + 2]), 0.f);
    v.w = fmaxf(fmaf(v.w, sa[cb + 3], sc[cb + 3]), 0.f);
    dh[i] = make_uint2(pack_hi2(v.x, v.y), pack_hi2(v.z, v.w));
    dl[i] = make_uint2(pack_lo2(v.x, v.y), pack_lo2(v.z, v.w));
}

// ---------------------------------------------------------------------------
// 3-NN (proven): key d' = ||p||^2 - 2 q.p via (-2x,-2y,-2z,||p||^2) staging.
// ---------------------------------------------------------------------------
__global__ __launch_bounds__(256) void knn_kernel(
    const float* __restrict__ xyz1, const float* __restrict__ xyz2,
    int* __restrict__ oidx, float* __restrict__ ow)
{
    __shared__ float4 sp[2048];
    const int b = blockIdx.y;
    const int n = blockIdx.x * 256 + threadIdx.x;

    const float* q = xyz1 + ((size_t)b * NN + n) * 3;
    const float qx = q[0], qy = q[1], qz = q[2];

    float b0v = 1e30f, b1v = 1e30f, b2v = 1e30f;
    int   i0 = 0, i1 = 0, i2 = 0;

    auto insert = [&](float d, int s) {
        if (d < b2v) {
            if (d < b1v) {
                b2v = b1v; i2 = i1;
                if (d < b0v) { b1v = b0v; i1 = i0; b0v = d; i0 = s; }
                else         { b1v = d;  i1 = s; }
            } else { b2v = d; i2 = s; }
        }
    };

    for (int c0 = 0; c0 < SS; c0 += 2048) {
        __syncthreads();
        #pragma unroll
        for (int r = 0; r < 8; r++) {
            int s = threadIdx.x + r * 256;
            const float* p = xyz2 + ((size_t)b * SS + c0 + s) * 3;
            float x = p[0], y = p[1], z = p[2];
            sp[s] = make_float4(-2.f * x, -2.f * y, -2.f * z, x * x + y * y + z * z);
        }
        __syncthreads();

        #pragma unroll 4
        for (int j = 0; j < 2048; j += 2) {
            float4 p0 = sp[j];
            float4 p1 = sp[j + 1];
            float d0 = fmaf(qx, p0.x, fmaf(qy, p0.y, fmaf(qz, p0.z, p0.w)));
            float d1 = fmaf(qx, p1.x, fmaf(qy, p1.y, fmaf(qz, p1.z, p1.w)));
            if (fminf(d0, d1) < b2v) {
                insert(d0, c0 + j);
                insert(d1, c0 + j + 1);
            }
        }
    }

    const float qn = qx * qx + qy * qy + qz * qz;
    float d0 = fmaxf(b0v + qn, 0.f);
    float d1 = fmaxf(b1v + qn, 0.f);
    float d2 = fmaxf(b2v + qn, 0.f);
    float r0 = 1.f / (d0 + 1e-8f);
    float r1 = 1.f / (d1 + 1e-8f);
    float r2 = 1.f / (d2 + 1e-8f);
    float inv = 1.f / (r0 + r1 + r2);

    size_t o = ((size_t)b * NN + n) * 3;
    oidx[o + 0] = i0; oidx[o + 1] = i1; oidx[o + 2] = i2;
    ow[o + 0] = r0 * inv; ow[o + 1] = r1 * inv; ow[o + 2] = r2 * inv;
}

// ---------------------------------------------------------------------------
// bf16-split tensor-core GEMM, cp.async 3-stage pipeline:
//   C[M,N] = A[M,K] @ Bw[N,K]^T,  D = Ah*Bh + Al*Bh + Ah*Bl  (fp32 accum)
// A pre-split (Ah,Al bf16, K-contiguous). CTA tile 128x64, BK=32, 8 warps
// (4x2) of the proven 32x32 warp tile; ldmatrix.x4 fragment loads.
// MODE 0: plain     MODE 1: +bias +3NN gather, fused stats
// MODE 2: +bias, fused stats (A already BN+ReLU'd by bnsplit)
// ---------------------------------------------------------------------------
#define STRB  80          // smem row stride bytes (40 bf16)
#define A_T   10240       // 128*80
#define B_T   5120        // 64*80
#define STGB  30720       // per-stage: Ah,Al,Bh,Bl
#define NSTG  3
#define SM_BIAS 92160
#define SM_SUM  92416
#define SM_SQ   92672
#define SM_SZ   92928

__device__ __forceinline__ void mma16816(float* d, const uint32_t* a, const uint32_t* b) {
    asm volatile(
        "mma.sync.aligned.m16n8k16.row.col.f32.bf16.bf16.f32 "
        "{%0,%1,%2,%3}, {%4,%5,%6,%7}, {%8,%9}, {%0,%1,%2,%3};"
        : "+f"(d[0]), "+f"(d[1]), "+f"(d[2]), "+f"(d[3])
        : "r"(a[0]), "r"(a[1]), "r"(a[2]), "r"(a[3]), "r"(b[0]), "r"(b[1]));
}
__device__ __forceinline__ void ldsm4(uint32_t* r, uint32_t addr) {
    asm volatile("ldmatrix.sync.aligned.m8n8.x4.shared.b16 {%0,%1,%2,%3}, [%4];"
        : "=r"(r[0]), "=r"(r[1]), "=r"(r[2]), "=r"(r[3]) : "r"(addr));
}
__device__ __forceinline__ uint32_t smem_u32(const void* p) {
    uint32_t a;
    asm("{ .reg .u64 t; cvta.to.shared.u64 t, %1; cvt.u32.u64 %0, t; }" : "=r"(a) : "l"(p));
    return a;
}
__device__ __forceinline__ void cpasync16(uint32_t s, const void* g) {
    asm volatile("cp.async.cg.shared.global [%0], [%1], 16;" :: "r"(s), "l"(g));
}
#define CP_COMMIT() asm volatile("cp.async.commit_group;" ::: "memory")
#define CP_WAIT1()  asm volatile("cp.async.wait_group 1;" ::: "memory")

template<int MODE, int KTOT>
__global__ __launch_bounds__(256, 2) void mma_gemm(
    const __nv_bfloat16* __restrict__ Ah, const __nv_bfloat16* __restrict__ Al,
    const __nv_bfloat16* __restrict__ Bh, const __nv_bfloat16* __restrict__ Bl,
    float* __restrict__ C, int ldc,
    const float* __restrict__ bias,
    const float* __restrict__ p2w, const int* __restrict__ gidx,
    const float* __restrict__ gw,
    float* __restrict__ gsum, float* __restrict__ gsq)
{
    extern __shared__ char sm[];
    const uint32_t sbase = smem_u32(sm);
    const int tid = threadIdx.x;
    const int m0 = blockIdx.y * 128;
    const int n0 = blockIdx.x * 64;

    float* sbias = (float*)(sm + SM_BIAS);
    float* ssum  = (float*)(sm + SM_SUM);
    float* ssq   = (float*)(sm + SM_SQ);
    if (MODE != 0 && tid < 64) sbias[tid] = bias[n0 + tid];
    if (MODE != 0 && tid < 128) { if (tid < 64) ssum[tid] = 0.f; else ssq[tid - 64] = 0.f; }
    __syncthreads();

    // cp.async issue mapping: 256 threads; A rows rA, rA+64; B row rA.
    const int rA = tid >> 2;                 // 0..63
    const int sA = (tid & 3) * 16;           // 16B segment within 64B row-chunk
    const int kE = sA >> 1;                  // element offset within chunk

    auto issue = [&](int st, int kc) {
        const uint32_t base = sbase + st * STGB;
        const int ke = kc * 32 + kE;
        const uint32_t s0 = base + rA * STRB + sA;
        const uint32_t s1 = base + (rA + 64) * STRB + sA;
        cpasync16(s0,        Ah + (size_t)(m0 + rA)      * KTOT + ke);
        cpasync16(s1,        Ah + (size_t)(m0 + rA + 64) * KTOT + ke);
        cpasync16(s0 + A_T,  Al + (size_t)(m0 + rA)      * KTOT + ke);
        cpasync16(s1 + A_T,  Al + (size_t)(m0 + rA + 64) * KTOT + ke);
        const uint32_t sb = base + 2 * A_T + rA * STRB + sA;
        cpasync16(sb,       Bh + (size_t)(n0 + rA) * KTOT + ke);
        cpasync16(sb + B_T, Bl + (size_t)(n0 + rA) * KTOT + ke);
    };

    const int wid = tid >> 5, l = tid & 31;
    const int wm = (wid >> 1) * 32, wn = (wid & 1) * 32;
    const int lr = l >> 2, lc = l & 3;

    float acc[2][4][4];
    #pragma unroll
    for (int mi = 0; mi < 2; mi++)
        #pragma unroll
        for (int ni = 0; ni < 4; ni++)
            #pragma unroll
            for (int j = 0; j < 4; j++) acc[mi][ni][j] = 0.f;

    // ldmatrix per-lane base addresses (within stage 0) — proven mapping
    const uint32_t a_lane = sbase +
        (uint32_t)((wm + (l & 15)) * STRB + (l >> 4) * 16);
    const uint32_t b_lane = sbase +
        (uint32_t)(2 * A_T + (wn + (l & 7) + ((l >> 4) & 1) * 8) * STRB + ((l >> 3) & 1) * 16);

    auto comp = [&](int st) {
        const uint32_t ab = a_lane + st * STGB;
        const uint32_t bb = b_lane + st * STGB;
        #pragma unroll
        for (int ks = 0; ks < 2; ks++) {
            uint32_t ah[2][4], al[2][4], bh[2][4], bl[2][4];
            #pragma unroll
            for (int mi = 0; mi < 2; mi++) {
                uint32_t a = ab + mi * (16 * STRB) + ks * 32;
                ldsm4(ah[mi], a);
                ldsm4(al[mi], a + A_T);
            }
            #pragma unroll
            for (int ni2 = 0; ni2 < 2; ni2++) {
                uint32_t b = bb + ni2 * (16 * STRB) + ks * 32;
                ldsm4(bh[ni2], b);
                ldsm4(bl[ni2], b + B_T);
            }
            #pragma unroll
            for (int mi = 0; mi < 2; mi++)
                #pragma unroll
                for (int ni = 0; ni < 4; ni++) {
                    const uint32_t* bhf = &bh[ni >> 1][(ni & 1) * 2];
                    const uint32_t* blf = &bl[ni >> 1][(ni & 1) * 2];
                    mma16816(acc[mi][ni], ah[mi], bhf);
                    mma16816(acc[mi][ni], al[mi], bhf);
                    mma16816(acc[mi][ni], ah[mi], blf);
                }
        }
    };

    constexpr int nch = KTOT / 32;
    // prologue: stages 0,1 in flight
    issue(0, 0); CP_COMMIT();
    issue(1, 1); CP_COMMIT();
    #pragma unroll
    for (int kc = 0; kc < nch; kc++) {
        CP_WAIT1();                 // stage kc complete (see count proof)
        __syncthreads();
        if (kc + 2 < nch) issue((kc + 2) % NSTG, kc + 2);
        CP_COMMIT();                // empty group in tail keeps counts aligned
        comp(kc % NSTG);
    }

    // --- epilogue: bias / gather / store + fused per-channel stats
    float fs[8], fq[8];
    #pragma unroll
    for (int i = 0; i < 8; i++) { fs[i] = 0.f; fq[i] = 0.f; }

    #pragma unroll
    for (int mi = 0; mi < 2; mi++) {
        #pragma unroll
        for (int half = 0; half < 2; half++) {
            const int gm = m0 + wm + mi * 16 + half * 8 + lr;
            const float *P0 = nullptr, *P1 = nullptr, *P2 = nullptr;
            float w0 = 0.f, w1 = 0.f, w2 = 0.f;
            if (MODE == 1) {
                const int bb_ = gm >> 14;                // NN = 16384
                int i0 = gidx[gm * 3 + 0], i1 = gidx[gm * 3 + 1], i2 = gidx[gm * 3 + 2];
                w0 = gw[gm * 3 + 0]; w1 = gw[gm * 3 + 1]; w2 = gw[gm * 3 + 2];
                P0 = p2w + ((size_t)bb_ * SS + i0) * O1 + n0;
                P1 = p2w + ((size_t)bb_ * SS + i1) * O1 + n0;
                P2 = p2w + ((size_t)bb_ * SS + i2) * O1 + n0;
            }
            float* Cp = C + (size_t)gm * ldc + n0;
            #pragma unroll
            for (int ni = 0; ni < 4; ni++) {
                const int col = wn + ni * 8 + lc * 2;
                float x = acc[mi][ni][half * 2 + 0];
                float y = acc[mi][ni][half * 2 + 1];
                if (MODE != 0) { x += sbias[col]; y += sbias[col + 1]; }
                if (MODE == 1) {
                    float2 q0 = *(const float2*)(P0 + col);
                    float2 q1 = *(const float2*)(P1 + col);
                    float2 q2 = *(const float2*)(P2 + col);
                    x += w0 * q0.x + w1 * q1.x + w2 * q2.x;
                    y += w0 * q0.y + w1 * q1.y + w2 * q2.y;
                }
                if (MODE != 0) {
                    fs[ni * 2 + 0] += x; fq[ni * 2 + 0] = fmaf(x, x, fq[ni * 2 + 0]);
                    fs[ni * 2 + 1] += y; fq[ni * 2 + 1] = fmaf(y, y, fq[ni * 2 + 1]);
                }
                *(float2*)(Cp + col) = make_float2(x, y);
            }
        }
    }

    if (MODE != 0) {
        #pragma unroll
        for (int i = 0; i < 8; i++) {
            fs[i] += __shfl_xor_sync(0xFFFFFFFFu, fs[i], 4);
            fs[i] += __shfl_xor_sync(0xFFFFFFFFu, fs[i], 8);
            fs[i] += __shfl_xor_sync(0xFFFFFFFFu, fs[i], 16);
            fq[i] += __shfl_xor_sync(0xFFFFFFFFu, fq[i], 4);
            fq[i] += __shfl_xor_sync(0xFFFFFFFFu, fq[i], 8);
            fq[i] += __shfl_xor_sync(0xFFFFFFFFu, fq[i], 16);
        }
        if (lr == 0) {
            #pragma unroll
            for (int ni = 0; ni < 4; ni++) {
                int col = wn + ni * 8 + lc * 2;
                atomicAdd(&ssum[col],     fs[ni * 2 + 0]);
                atomicAdd(&ssum[col + 1], fs[ni * 2 + 1]);
                atomicAdd(&ssq[col],      fq[ni * 2 + 0]);
                atomicAdd(&ssq[col + 1],  fq[ni * 2 + 1]);
            }
        }
        __syncthreads();
        if (tid < 64) {
            atomicAdd(&gsum[n0 + tid], ssum[tid]);
            atomicAdd(&gsq[n0 + tid],  ssq[tid]);
        }
    }
}

// ---------------------------------------------------------------------------
// Final BN2+ReLU apply, with inline coefficient computation.
// ---------------------------------------------------------------------------
__global__ void bnrelu_kernel(float* __restrict__ out,
                              const float* __restrict__ sum, const float* __restrict__ sq,
                              const float* __restrict__ gamma, const float* __restrict__ beta)
{
    __shared__ float sa[O2], sc[O2];
    const int tid = threadIdx.x;
    if (tid < O2) {
        const float Minv = 1.f / (float)MTOT;
        float mean = sum[tid] * Minv;
        float var  = fmaf(-mean, mean, sq[tid] * Minv);
        float s = gamma[tid] * rsqrtf(var + 1e-5f);
        sa[tid] = s;
        sc[tid] = fmaf(-mean, s, beta[tid]);
    }
    __syncthreads();

    const size_t i = (size_t)blockIdx.x * blockDim.x + tid;
    float4 v = ((float4*)out)[i];
    const int cb = (int)((i * 4) & (O2 - 1));
    v.x = fmaxf(fmaf(v.x, sa[cb + 0], sc[cb + 0]), 0.f);
    v.y = fmaxf(fmaf(v.y, sa[cb + 1], sc[cb + 1]), 0.f);
    v.z = fmaxf(fmaf(v.z, sa[cb + 2], sc[cb + 2]), 0.f);
    v.w = fmaxf(fmaf(v.w, sa[cb + 3], sc[cb + 3]), 0.f);
    ((float4*)out)[i] = v;
}

// ---------------------------------------------------------------------------
extern "C" void kernel_launch(void* const* d_in, const int* in_sizes, int n_in,
                              void* d_out, int out_size)
{
    const float* xyz1    = (const float*)d_in[0];
    const float* xyz2    = (const float*)d_in[1];
    const float* points1 = (const float*)d_in[2];
    const float* points2 = (const float*)d_in[3];
    const float* W1      = (const float*)d_in[4];
    const float* b1      = (const float*)d_in[5];
    const float* g1      = (const float*)d_in[6];
    const float* be1     = (const float*)d_in[7];
    const float* W2      = (const float*)d_in[8];
    const float* b2      = (const float*)d_in[9];
    const float* g2      = (const float*)d_in[10];
    const float* be2     = (const float*)d_in[11];
    float* out = (float*)d_out;

    float *p2w, *h1, *wp, *sum1, *sq1, *sum2, *sq2;
    int* idxp;
    __nv_bfloat16 *b0h, *b0l, *b1h, *b1l, *b2h, *b2l;
    __nv_bfloat16 *a0h, *a0l, *a1h, *a1l, *h2h, *h2l;
    cudaGetSymbolAddress((void**)&p2w,  g_p2w);
    cudaGetSymbolAddress((void**)&h1,   g_h1);
    cudaGetSymbolAddress((void**)&idxp, g_idx);
    cudaGetSymbolAddress((void**)&wp,   g_w);
    cudaGetSymbolAddress((void**)&sum1, g_sum1);
    cudaGetSymbolAddress((void**)&sq1,  g_sq1);
    cudaGetSymbolAddress((void**)&sum2, g_sum2);
    cudaGetSymbolAddress((void**)&sq2,  g_sq2);
    cudaGetSymbolAddress((void**)&b0h,  g_b0h);
    cudaGetSymbolAddress((void**)&b0l,  g_b0l);
    cudaGetSymbolAddress((void**)&b1h,  g_b1h);
    cudaGetSymbolAddress((void**)&b1l,  g_b1l);
    cudaGetSymbolAddress((void**)&b2h,  g_b2h);
    cudaGetSymbolAddress((void**)&b2l,  g_b2l);
    cudaGetSymbolAddress((void**)&a0h,  g_a0h);
    cudaGetSymbolAddress((void**)&a0l,  g_a0l);
    cudaGetSymbolAddress((void**)&a1h,  g_a1h);
    cudaGetSymbolAddress((void**)&a1l,  g_a1l);
    cudaGetSymbolAddress((void**)&h2h,  g_h2h);
    cudaGetSymbolAddress((void**)&h2l,  g_h2l);

    cudaFuncSetAttribute(mma_gemm<0, 256>, cudaFuncAttributeMaxDynamicSharedMemorySize, SM_SZ);
    cudaFuncSetAttribute(mma_gemm<1, 128>, cudaFuncAttributeMaxDynamicSharedMemorySize, SM_SZ);
    cudaFuncSetAttribute(mma_gemm<2, 256>, cudaFuncAttributeMaxDynamicSharedMemorySize, SM_SZ);

    // Side stream + events (created per call, intentionally leaked; only a
    // handful of invocations and handles participate in graph capture).
    cudaStream_t s1;
    cudaEvent_t evFork, evJoin;
    cudaStreamCreateWithFlags(&s1, cudaStreamNonBlocking);
    cudaEventCreateWithFlags(&evFork, cudaEventDisableTiming);
    cudaEventCreateWithFlags(&evJoin, cudaEventDisableTiming);

    // Fork: knn + points1 split on s1, overlapping zero/prep/split2/gemm0.
    cudaEventRecord(evFork, 0);
    cudaStreamWaitEvent(s1, evFork, 0);
    knn_kernel<<<dim3(NN / 256, BB), 256, 0, s1>>>(xyz1, xyz2, idxp, wp);
    split_kernel<<<(MTOT * D1 / 4) / 256, 256, 0, s1>>>(
        (const float4*)points1, (uint2*)a1h, (uint2*)a1l);
    cudaEventRecord(evJoin, s1);

    // Main stream
    zero_stats_kernel<<<1, 256>>>();
    prep_weights_kernel<<<(O1 * C1) / 256, 256>>>(W1, W2);
    split_kernel<<<(BB * SS * D2 / 4) / 256, 256>>>(
        (const float4*)points2, (uint2*)a0h, (uint2*)a0l);

    // gemm0: P2W = points2 @ W1b^T
    mma_gemm<0, 256><<<dim3(O1 / 64, (BB * SS) / 128), 256, SM_SZ>>>(
        a0h, a0l, b0h, b0l, p2w, O1,
        nullptr, nullptr, nullptr, nullptr, nullptr, nullptr);

    // Join: gemm1 needs knn results + points1 split.
    cudaStreamWaitEvent(0, evJoin, 0);

    // gemm1: h1 = points1 @ W1a^T + b1 + gather   (BN1 stats fused)
    mma_gemm<1, 128><<<dim3(O1 / 64, MTOT / 128), 256, SM_SZ>>>(
        a1h, a1l, b1h, b1l, h1, O1,
        b1, p2w, idxp, wp, sum1, sq1);

    // bnsplit: h2 = split(relu(bn1(h1)))   (BN1 coeffs inline)
    bnsplit_kernel<<<(MTOT * O1 / 4) / 256, 256>>>(
        (const float4*)h1, (uint2*)h2h, (uint2*)h2l, sum1, sq1, g1, be1);

    // gemm2: out = h2 @ W2^T + b2   (BN2 stats fused)
    mma_gemm<2, 256><<<dim3(O2 / 64, MTOT / 128), 256, SM_SZ>>>(
        h2h, h2l, b2h, b2l, out, O2,
        b2, nullptr, nullptr, nullptr, sum2, sq2);

    // BN2 + ReLU in place (coeffs inline)
    bnrelu_kernel<<<(MTOT * O2 / 4) / 256, 256>>>(out, sum2, sq2, g2, be2);
}